// round 1
// baseline (speedup 1.0000x reference)
#include <cuda_runtime.h>
#include <cuda_bf16.h>
#include <math.h>

// ---------------- fixed problem dims ----------------
#define BB   2
#define TT4  4
#define N4   4096
#define CC   256
#define NC   150
#define TN   16384      // T*N
#define HID  1024
#define NH   8
#define HD   32
#define HH   64
#define WW   64

#define OUT0_ELEMS 2097152      // B*N*C
#define CXZ_ELEMS  4915200      // B*nc*T*N
#define CTR_ELEMS  4915200

// ---------------- scratch (static device memory; no allocs) -------------
__device__ float g_cl[4915200];     // (B*T, nc, N)
__device__ float g_az[4915200];     // (B, nc, T*N)  scaled z rows (transposed)
__device__ float g_ac[4915200];     // (B, nc, T*N)  scaled cl rows (transposed)
__device__ float g_soft[4915200];   // (B*T, nc, N)
__device__ float g_cen[307200];     // (B*T, nc, C)
__device__ float g_cinln[76800];    // (B, nc, C)
__device__ float g_kbuf[76800];
__device__ float g_vbuf[76800];
__device__ float g_q[2097152];
__device__ float g_o[2097152];
__device__ float g_oproj[2097152];
__device__ float g_out1[2097152];
__device__ float g_h1[8388608];     // (B, N, HID)
__device__ float g_g[8388608];
__device__ float g_h2[2097152];

// ---------------- helpers ----------------
__device__ __forceinline__ float block_reduce_sum(float v, float* sbuf) {
    int tid = threadIdx.x;
    sbuf[tid] = v; __syncthreads();
    for (int s = blockDim.x >> 1; s > 0; s >>= 1) {
        if (tid < s) sbuf[tid] += sbuf[tid + s];
        __syncthreads();
    }
    float r = sbuf[0]; __syncthreads();
    return r;
}
__device__ __forceinline__ float block_reduce_max(float v, float* sbuf) {
    int tid = threadIdx.x;
    sbuf[tid] = v; __syncthreads();
    for (int s = blockDim.x >> 1; s > 0; s >>= 1) {
        if (tid < s) sbuf[tid] = fmaxf(sbuf[tid], sbuf[tid + s]);
        __syncthreads();
    }
    float r = sbuf[0]; __syncthreads();
    return r;
}

// ---------------- generic tiled GEMM:  C = (A @ B^T + bias) * scale -----
// A: (M,K) row-major.  B: (N,K) row-major.  C: (M,N) row-major.
#define BM 64
#define BN 64
#define BK 16
__global__ void gemm_tb_kernel(const float* __restrict__ A,
                               const float* __restrict__ B,
                               const float* __restrict__ bias,
                               float* __restrict__ C,
                               int M, int N, int K, float scale)
{
    __shared__ float As[BK][BM];
    __shared__ float Bs[BK][BN];
    int tid = threadIdx.x;
    int tx = tid & 15, ty = tid >> 4;
    int m0 = blockIdx.y * BM, n0 = blockIdx.x * BN;
    float acc[4][4] = {};
    for (int k0 = 0; k0 < K; k0 += BK) {
        #pragma unroll
        for (int j = 0; j < 4; j++) {
            int idx = tid + j * 256;
            int ml = idx / BK, kl = idx % BK;
            int m = m0 + ml, k = k0 + kl;
            As[kl][ml] = (m < M) ? A[(size_t)m * K + k] : 0.f;
        }
        #pragma unroll
        for (int j = 0; j < 4; j++) {
            int idx = tid + j * 256;
            int nl = idx / BK, kl = idx % BK;
            int n = n0 + nl, k = k0 + kl;
            Bs[kl][nl] = (n < N) ? B[(size_t)n * K + k] : 0.f;
        }
        __syncthreads();
        #pragma unroll
        for (int kk = 0; kk < BK; kk++) {
            float a[4], b[4];
            *(float4*)a = *(const float4*)&As[kk][ty * 4];
            *(float4*)b = *(const float4*)&Bs[kk][tx * 4];
            #pragma unroll
            for (int i = 0; i < 4; i++)
                #pragma unroll
                for (int j = 0; j < 4; j++)
                    acc[i][j] += a[i] * b[j];
        }
        __syncthreads();
    }
    #pragma unroll
    for (int i = 0; i < 4; i++) {
        int m = m0 + ty * 4 + i;
        if (m >= M) continue;
        #pragma unroll
        for (int j = 0; j < 4; j++) {
            int n = n0 + tx * 4 + j;
            if (n >= N) continue;
            float v = acc[i][j];
            if (bias) v += bias[n];
            C[(size_t)m * N + n] = v * scale;
        }
    }
}

// ---- cl GEMM: cl[bt,k,n] = sum_c w[k,c] * xf[bt,n,c]  (M=nc,N=4096,K=256)
__global__ void cl_gemm_kernel(const float* __restrict__ w,
                               const float* __restrict__ x,
                               const float* __restrict__ mem,
                               float* __restrict__ cl)
{
    int bt = blockIdx.z;
    int b = bt / TT4, t = bt % TT4;
    const float* Bp = (t < 3) ? (mem + (size_t)(b * 3 + t) * N4 * CC)
                              : (x + (size_t)b * N4 * CC);
    float* Cp = cl + (size_t)bt * NC * N4;

    __shared__ float As[BK][BM];
    __shared__ float Bs[BK][BN];
    int tid = threadIdx.x;
    int tx = tid & 15, ty = tid >> 4;
    int m0 = blockIdx.y * BM, n0 = blockIdx.x * BN;
    float acc[4][4] = {};
    for (int k0 = 0; k0 < CC; k0 += BK) {
        #pragma unroll
        for (int j = 0; j < 4; j++) {
            int idx = tid + j * 256;
            int ml = idx / BK, kl = idx % BK;
            int m = m0 + ml;
            As[kl][ml] = (m < NC) ? w[(size_t)m * CC + k0 + kl] : 0.f;
        }
        #pragma unroll
        for (int j = 0; j < 4; j++) {
            int idx = tid + j * 256;
            int nl = idx / BK, kl = idx % BK;
            Bs[kl][nl] = Bp[(size_t)(n0 + nl) * CC + k0 + kl];
        }
        __syncthreads();
        #pragma unroll
        for (int kk = 0; kk < BK; kk++) {
            float a[4], b[4];
            *(float4*)a = *(const float4*)&As[kk][ty * 4];
            *(float4*)b = *(const float4*)&Bs[kk][tx * 4];
            #pragma unroll
            for (int i = 0; i < 4; i++)
                #pragma unroll
                for (int j = 0; j < 4; j++)
                    acc[i][j] += a[i] * b[j];
        }
        __syncthreads();
    }
    #pragma unroll
    for (int i = 0; i < 4; i++) {
        int m = m0 + ty * 4 + i;
        if (m >= NC) continue;
        #pragma unroll
        for (int j = 0; j < 4; j++)
            Cp[(size_t)m * N4 + n0 + tx * 4 + j] = acc[i][j];
    }
}

// ---- prompt scaling: per row m of (B,TN): cos against p1/p2, write scaled
//      az[b,k,m] = 0.5*cz*z[b,k,m], ac[b,k,m] = 0.5*cc*cl[b,t,k,n]
__global__ void prompt_scale_kernel(const float* __restrict__ z,
                                    const float* __restrict__ cl,
                                    const float* __restrict__ p1,
                                    const float* __restrict__ p2,
                                    float* __restrict__ az,
                                    float* __restrict__ ac)
{
    int m = blockIdx.x * blockDim.x + threadIdx.x;
    int b = blockIdx.z;
    if (m >= TN) return;
    int t = m / N4, n = m % N4;
    const float* zrow = z + (size_t)b * NC * TN + m;
    const float* crow = cl + ((size_t)(b * TT4 + t) * NC) * N4 + n;
    float dz = 0, nz = 0, dc = 0, ncs = 0, p1n = 0, p2n = 0;
    for (int k = 0; k < NC; k++) {
        float zv = zrow[(size_t)k * TN];
        float cv = crow[(size_t)k * N4];
        float a = p1[k], bb = p2[k];
        dz += zv * a; nz += zv * zv; p1n += a * a;
        dc += cv * bb; ncs += cv * cv; p2n += bb * bb;
    }
    float cz = dz / (fmaxf(sqrtf(nz), 1e-12f) * fmaxf(sqrtf(p1n), 1e-12f));
    cz = fminf(fmaxf(cz, 0.f), 1.f) * 0.5f;
    float cc = dc / (fmaxf(sqrtf(ncs), 1e-12f) * fmaxf(sqrtf(p2n), 1e-12f));
    cc = fminf(fmaxf(cc, 0.f), 1.f) * 0.5f;
    float* azp = az + (size_t)b * NC * TN + m;
    float* acp = ac + (size_t)b * NC * TN + m;
    for (int k = 0; k < NC; k++) {
        azp[(size_t)k * TN] = cz * zrow[(size_t)k * TN];
        acp[(size_t)k * TN] = cc * crow[(size_t)k * N4];
    }
}

// ---- combine GEMM: cxz[b,j,m] = sum_k tdt1[k,j]*az[b,k,m] + tdt2[k,j]*ac[b,k,m]
__global__ void comb_gemm_kernel(const float* __restrict__ tdt1,
                                 const float* __restrict__ tdt2,
                                 const float* __restrict__ az,
                                 const float* __restrict__ ac,
                                 float* __restrict__ cxz)
{
    int b = blockIdx.z;
    int j0 = blockIdx.y * BM, m0 = blockIdx.x * BN;
    __shared__ float As[BK][BM];
    __shared__ float Bs[BK][BN];
    int tid = threadIdx.x;
    int tx = tid & 15, ty = tid >> 4;
    float acc[4][4] = {};
    for (int s = 0; s < 2; s++) {
        const float* tdt = s ? tdt2 : tdt1;
        const float* bz = (s ? ac : az) + (size_t)b * NC * TN;
        for (int k0 = 0; k0 < NC; k0 += BK) {
            #pragma unroll
            for (int j = 0; j < 4; j++) {
                int idx = tid + j * 256;
                int kl = idx / BM, jl = idx % BM;
                int k = k0 + kl, jj = j0 + jl;
                As[kl][jl] = (k < NC && jj < NC) ? tdt[(size_t)k * NC + jj] : 0.f;
            }
            #pragma unroll
            for (int j = 0; j < 4; j++) {
                int idx = tid + j * 256;
                int kl = idx / BN, ml = idx % BN;
                int k = k0 + kl;
                Bs[kl][ml] = (k < NC) ? bz[(size_t)k * TN + m0 + ml] : 0.f;
            }
            __syncthreads();
            #pragma unroll
            for (int kk = 0; kk < BK; kk++) {
                float a[4], bb[4];
                *(float4*)a  = *(const float4*)&As[kk][ty * 4];
                *(float4*)bb = *(const float4*)&Bs[kk][tx * 4];
                #pragma unroll
                for (int i = 0; i < 4; i++)
                    #pragma unroll
                    for (int j = 0; j < 4; j++)
                        acc[i][j] += a[i] * bb[j];
            }
            __syncthreads();
        }
    }
    #pragma unroll
    for (int i = 0; i < 4; i++) {
        int jj = j0 + ty * 4 + i;
        if (jj >= NC) continue;
        #pragma unroll
        for (int j = 0; j < 4; j++)
            cxz[((size_t)b * NC + jj) * TN + m0 + tx * 4 + j] = acc[i][j];
    }
}

// ---- center permute-copy: ctr[b,t,j,n] = cxz[b,j,t*N+n]
__global__ void center_copy_kernel(const float* __restrict__ cxz,
                                   float* __restrict__ ctr)
{
    int idx = blockIdx.x * blockDim.x + threadIdx.x;
    if (idx >= CTR_ELEMS) return;
    int n = idx & (N4 - 1);
    int r = idx >> 12;
    int j = r % NC;
    int bt = r / NC;
    int b = bt / TT4, t = bt % TT4;
    ctr[idx] = cxz[((size_t)b * NC + j) * TN + t * N4 + n];
}

// ---- softmax over n per (b,t,k) row, reading cxz rows in place ----
__global__ void softmax_kernel(const float* __restrict__ cxz,
                               float* __restrict__ soft)
{
    __shared__ float sbuf[256];
    int r = blockIdx.x;            // bt*NC + k
    int k = r % NC;
    int bt = r / NC;
    int b = bt / TT4, t = bt % TT4;
    const float* src = cxz + ((size_t)b * NC + k) * TN + t * N4;
    float* dst = soft + (size_t)r * N4;
    int tid = threadIdx.x;
    float mx = -3.4e38f;
    for (int i = tid; i < N4; i += 256) mx = fmaxf(mx, src[i]);
    mx = block_reduce_max(mx, sbuf);
    float s = 0.f;
    for (int i = tid; i < N4; i += 256) {
        float e = expf(src[i] - mx);
        dst[i] = e;
        s += e;
    }
    s = block_reduce_sum(s, sbuf);
    float inv = 1.f / s;
    for (int i = tid; i < N4; i += 256) dst[i] *= inv;
}

// ---- cen GEMM (NN): cen[bt,k,c] = sum_n soft[bt,k,n]*xf[bt,n,c]
__global__ void cen_gemm_kernel(const float* __restrict__ soft,
                                const float* __restrict__ x,
                                const float* __restrict__ mem,
                                float* __restrict__ cen)
{
    int bt = blockIdx.z;
    int b = bt / TT4, t = bt % TT4;
    const float* A = soft + (size_t)bt * NC * N4;
    const float* Bp = (t < 3) ? (mem + (size_t)(b * 3 + t) * N4 * CC)
                              : (x + (size_t)b * N4 * CC);
    float* Cp = cen + (size_t)bt * NC * CC;

    __shared__ float As[BK][BM];
    __shared__ float Bs[BK][BN];
    int tid = threadIdx.x;
    int tx = tid & 15, ty = tid >> 4;
    int m0 = blockIdx.y * BM, n0 = blockIdx.x * BN;
    float acc[4][4] = {};
    for (int k0 = 0; k0 < N4; k0 += BK) {
        #pragma unroll
        for (int j = 0; j < 4; j++) {
            int idx = tid + j * 256;
            int ml = idx / BK, kl = idx % BK;
            int m = m0 + ml;
            As[kl][ml] = (m < NC) ? A[(size_t)m * N4 + k0 + kl] : 0.f;
        }
        #pragma unroll
        for (int j = 0; j < 4; j++) {
            int idx = tid + j * 256;
            int kl = idx / BN, nl = idx % BN;
            Bs[kl][nl] = Bp[(size_t)(k0 + kl) * CC + n0 + nl];
        }
        __syncthreads();
        #pragma unroll
        for (int kk = 0; kk < BK; kk++) {
            float a[4], b[4];
            *(float4*)a = *(const float4*)&As[kk][ty * 4];
            *(float4*)b = *(const float4*)&Bs[kk][tx * 4];
            #pragma unroll
            for (int i = 0; i < 4; i++)
                #pragma unroll
                for (int j = 0; j < 4; j++)
                    acc[i][j] += a[i] * b[j];
        }
        __syncthreads();
    }
    #pragma unroll
    for (int i = 0; i < 4; i++) {
        int m = m0 + ty * 4 + i;
        if (m >= NC) continue;
        #pragma unroll
        for (int j = 0; j < 4; j++)
            Cp[(size_t)m * CC + n0 + tx * 4 + j] = acc[i][j];
    }
}

// ---- C_in gating + LayerNorm: one block per (b,k) ----
__global__ void cin_kernel(const float* __restrict__ cen,
                           const float* __restrict__ alpha,
                           const float* __restrict__ beta,
                           const float* __restrict__ nw,
                           const float* __restrict__ nb,
                           float* __restrict__ cinln)
{
    __shared__ float sbuf[256];
    int bk = blockIdx.x;
    int b = bk / NC, k = bk % NC;
    int c = threadIdx.x;
    float last = cen[((size_t)(b * TT4 + 3) * NC + k) * CC + c];
    float pv[3];
    #pragma unroll
    for (int t = 0; t < 3; t++)
        pv[t] = cen[((size_t)(b * TT4 + t) * NC + k) * CC + c];
    float nl = block_reduce_sum(last * last, sbuf);
    float al = alpha[0], be = beta[0];
    float g[3];
    #pragma unroll
    for (int t = 0; t < 3; t++) {
        float dt = block_reduce_sum(last * pv[t], sbuf);
        float np = block_reduce_sum(pv[t] * pv[t], sbuf);
        float denom = fmaxf(sqrtf(nl) * sqrtf(np), 1e-8f);
        g[t] = 1.f / (1.f + expf(-(be + al * dt / denom)));
    }
    float cin = last + g[0] * pv[0] + g[1] * pv[1] + g[2] * pv[2];
    float mean = block_reduce_sum(cin, sbuf) * (1.f / CC);
    float d = cin - mean;
    float var = block_reduce_sum(d * d, sbuf) * (1.f / CC);
    cinln[((size_t)b * NC + k) * CC + c] = d * rsqrtf(var + 1e-5f) * nw[c] + nb[c];
}

// ---- attention: one warp per query n, K/V staged in SMEM ----
__global__ void attn_kernel(const float* __restrict__ q,
                            const float* __restrict__ kbuf,
                            const float* __restrict__ vbuf,
                            float* __restrict__ o)
{
    __shared__ float kh[NC * 33];
    __shared__ float vh[NC * 33];
    int b = blockIdx.z, h = blockIdx.y;
    int tid = threadIdx.x;
    int warp = tid >> 5, lane = tid & 31;
    for (int idx = tid; idx < NC * HD; idx += blockDim.x) {
        int kk = idx / HD, d = idx % HD;
        kh[kk * 33 + d] = kbuf[((size_t)b * NC + kk) * CC + h * HD + d];
        vh[kk * 33 + d] = vbuf[((size_t)b * NC + kk) * CC + h * HD + d];
    }
    __syncthreads();
    const unsigned FULL = 0xffffffffu;
    for (int ni = warp; ni < 256; ni += 8) {
        int n = blockIdx.x * 256 + ni;
        float qv = q[((size_t)b * N4 + n) * CC + h * HD + lane];
        float lg[5];
        #pragma unroll
        for (int i = 0; i < 5; i++) {
            int kk = lane + 32 * i;
            int kks = (kk < NC) ? kk : (NC - 1);
            float acc = 0.f;
            #pragma unroll
            for (int d = 0; d < 32; d++) {
                float qd = __shfl_sync(FULL, qv, d);
                acc += qd * kh[kks * 33 + d];
            }
            lg[i] = (kk < NC) ? acc : -3.4e38f;
        }
        float mx = lg[0];
        #pragma unroll
        for (int i = 1; i < 5; i++) mx = fmaxf(mx, lg[i]);
        #pragma unroll
        for (int off = 16; off > 0; off >>= 1)
            mx = fmaxf(mx, __shfl_xor_sync(FULL, mx, off));
        float p[5], s = 0.f;
        #pragma unroll
        for (int i = 0; i < 5; i++) { p[i] = expf(lg[i] - mx); s += p[i]; }
        #pragma unroll
        for (int off = 16; off > 0; off >>= 1)
            s += __shfl_xor_sync(FULL, s, off);
        float inv = 1.f / s;
        float od = 0.f;
        #pragma unroll
        for (int i = 0; i < 5; i++) {
            float pi = p[i] * inv;
            #pragma unroll
            for (int l = 0; l < 32; l++) {
                float a = __shfl_sync(FULL, pi, l);
                int kk = l + 32 * i;
                if (kk < NC) od += a * vh[kk * 33 + lane];
            }
        }
        o[((size_t)b * N4 + n) * CC + h * HD + lane] = od;
    }
}

// ---- out = base + LayerNorm(xin) per row of C ----
__global__ void ln_add_kernel(const float* __restrict__ base,
                              const float* __restrict__ xin,
                              const float* __restrict__ nw,
                              const float* __restrict__ nb,
                              float* __restrict__ out)
{
    __shared__ float sbuf[256];
    size_t row = blockIdx.x;
    int c = threadIdx.x;
    float v = xin[row * CC + c];
    float mean = block_reduce_sum(v, sbuf) * (1.f / CC);
    float d = v - mean;
    float var = block_reduce_sum(d * d, sbuf) * (1.f / CC);
    out[row * CC + c] = base[row * CC + c] + d * rsqrtf(var + 1e-5f) * nw[c] + nb[c];
}

// ---- depthwise 3x3 SAME conv + bias + exact GELU ----
__global__ void dwconv_gelu_kernel(const float* __restrict__ h1,
                                   const float* __restrict__ dw_w,
                                   const float* __restrict__ dw_b,
                                   float* __restrict__ g)
{
    int idx = blockIdx.x * blockDim.x + threadIdx.x;
    if (idx >= BB * N4 * HID) return;
    int ch = idx & (HID - 1);
    int r = idx >> 10;
    int n = r & (N4 - 1);
    int b = r >> 12;
    int y = n >> 6, x = n & 63;
    float acc = dw_b[ch];
    #pragma unroll
    for (int dy = 0; dy < 3; dy++) {
        int yy = y + dy - 1;
        if (yy < 0 || yy >= HH) continue;
        #pragma unroll
        for (int dx = 0; dx < 3; dx++) {
            int xx = x + dx - 1;
            if (xx < 0 || xx >= WW) continue;
            acc += h1[((size_t)b * N4 + yy * WW + xx) * HID + ch] *
                   dw_w[ch * 9 + dy * 3 + dx];
        }
    }
    // exact GELU
    g[idx] = 0.5f * acc * (1.0f + erff(acc * 0.70710678118654752f));
}

// ================= host launcher =================
extern "C" void kernel_launch(void* const* d_in, const int* in_sizes, int n_in,
                              void* d_out, int out_size)
{
    const float* x      = (const float*)d_in[0];
    const float* z      = (const float*)d_in[1];
    const float* mem    = (const float*)d_in[2];
    const float* cw     = (const float*)d_in[3];
    const float* p1     = (const float*)d_in[4];
    const float* tdt1   = (const float*)d_in[5];
    const float* p2     = (const float*)d_in[6];
    const float* tdt2   = (const float*)d_in[7];
    const float* alpha  = (const float*)d_in[8];
    const float* beta   = (const float*)d_in[9];
    const float* q_w    = (const float*)d_in[10];
    const float* q_b    = (const float*)d_in[11];
    const float* k_w    = (const float*)d_in[12];
    const float* k_b    = (const float*)d_in[13];
    const float* v_w    = (const float*)d_in[14];
    const float* v_b    = (const float*)d_in[15];
    const float* proj_w = (const float*)d_in[16];
    const float* proj_b = (const float*)d_in[17];
    const float* norm_w = (const float*)d_in[18];
    const float* norm_b = (const float*)d_in[19];
    const float* fc1_w  = (const float*)d_in[20];
    const float* fc1_b  = (const float*)d_in[21];
    const float* dw_w   = (const float*)d_in[22];
    const float* dw_b   = (const float*)d_in[23];
    const float* fc2_w  = (const float*)d_in[24];
    const float* fc2_b  = (const float*)d_in[25];

    float* out0 = (float*)d_out;
    float* cxz  = out0 + OUT0_ELEMS;
    float* ctr  = out0 + OUT0_ELEMS + CXZ_ELEMS;

    float *cl, *az, *ac, *soft, *cen, *cinln, *kb, *vb, *qb, *ob, *oproj,
          *out1, *h1, *gg, *h2;
    cudaGetSymbolAddress((void**)&cl,    g_cl);
    cudaGetSymbolAddress((void**)&az,    g_az);
    cudaGetSymbolAddress((void**)&ac,    g_ac);
    cudaGetSymbolAddress((void**)&soft,  g_soft);
    cudaGetSymbolAddress((void**)&cen,   g_cen);
    cudaGetSymbolAddress((void**)&cinln, g_cinln);
    cudaGetSymbolAddress((void**)&kb,    g_kbuf);
    cudaGetSymbolAddress((void**)&vb,    g_vbuf);
    cudaGetSymbolAddress((void**)&qb,    g_q);
    cudaGetSymbolAddress((void**)&ob,    g_o);
    cudaGetSymbolAddress((void**)&oproj, g_oproj);
    cudaGetSymbolAddress((void**)&out1,  g_out1);
    cudaGetSymbolAddress((void**)&h1,    g_h1);
    cudaGetSymbolAddress((void**)&gg,    g_g);
    cudaGetSymbolAddress((void**)&h2,    g_h2);

    // 1) cl[bt,k,n]
    cl_gemm_kernel<<<dim3(N4 / BN, 3, BB * TT4), 256>>>(cw, x, mem, cl);
    // 2) prompt cos + row scaling -> az, ac
    prompt_scale_kernel<<<dim3(TN / 256, 1, BB), 256>>>(z, cl, p1, p2, az, ac);
    // 3) combine GEMM -> cluster_x_z (output #2)
    comb_gemm_kernel<<<dim3(TN / BN, 3, BB), 256>>>(tdt1, tdt2, az, ac, cxz);
    // 4) center permute-copy (output #3)
    center_copy_kernel<<<(CTR_ELEMS + 255) / 256, 256>>>(cxz, ctr);
    // 5) softmax rows
    softmax_kernel<<<BB * TT4 * NC, 256>>>(cxz, soft);
    // 6) cen GEMM
    cen_gemm_kernel<<<dim3(CC / BN, 3, BB * TT4), 256>>>(soft, x, mem, cen);
    // 7) gating + LN -> C_in
    cin_kernel<<<BB * NC, 256>>>(cen, alpha, beta, norm_w, norm_b, cinln);
    // 8) k, v projections (M = B*nc = 300)
    gemm_tb_kernel<<<dim3(CC / BN, (BB * NC + BM - 1) / BM, 1), 256>>>(
        cinln, k_w, k_b, kb, BB * NC, CC, CC, 1.f);
    gemm_tb_kernel<<<dim3(CC / BN, (BB * NC + BM - 1) / BM, 1), 256>>>(
        cinln, v_w, v_b, vb, BB * NC, CC, CC, 1.f);
    // 9) q projection (scaled)
    gemm_tb_kernel<<<dim3(CC / BN, BB * N4 / BM, 1), 256>>>(
        x, q_w, q_b, qb, BB * N4, CC, CC, 0.17677669529663687f);
    // 10) attention
    attn_kernel<<<dim3(N4 / 256, NH, BB), 256>>>(qb, kb, vb, ob);
    // 11) output projection
    gemm_tb_kernel<<<dim3(CC / BN, BB * N4 / BM, 1), 256>>>(
        ob, proj_w, proj_b, oproj, BB * N4, CC, CC, 1.f);
    // 12) out1 = x + LN(oproj)
    ln_add_kernel<<<BB * N4, 256>>>(x, oproj, norm_w, norm_b, out1);
    // 13) fc1
    gemm_tb_kernel<<<dim3(HID / BN, BB * N4 / BM, 1), 256>>>(
        out1, fc1_w, fc1_b, h1, BB * N4, HID, CC, 1.f);
    // 14) depthwise conv + bias + gelu
    dwconv_gelu_kernel<<<(BB * N4 * HID + 255) / 256, 256>>>(h1, dw_w, dw_b, gg);
    // 15) fc2
    gemm_tb_kernel<<<dim3(CC / BN, BB * N4 / BM, 1), 256>>>(
        gg, fc2_w, fc2_b, h2, BB * N4, CC, HID, 1.f);
    // 16) final: out = out1 + LN(h2)   (output #1)
    ln_add_kernel<<<BB * N4, 256>>>(out1, h2, norm_w, norm_b, out0);
}

// round 3
// speedup vs baseline: 1.4405x; 1.4405x over previous
#include <cuda_runtime.h>
#include <math.h>

// ---------------- fixed problem dims ----------------
#define BB   2
#define TT4  4
#define N4   4096
#define CC   256
#define NC   150
#define TNE  16384
#define HID  1024
#define NH   8
#define HD   32
#define HH   64
#define WW   64

#define OUT0_ELEMS 2097152
#define CXZ_ELEMS  4915200

// ---------------- scratch ----------------
__device__ float g_cl[4915200];
__device__ float g_az[4915200];
__device__ float g_ac[4915200];
__device__ float g_soft[4915200];
__device__ float g_cen[307200];
__device__ float g_cinln[76800];
__device__ float g_kbuf[76800];
__device__ float g_vbuf[76800];
__device__ float g_q[2097152];
__device__ float g_o[2097152];
__device__ float g_oproj[2097152];
__device__ float g_out1[2097152];
__device__ float g_h1[8388608];
__device__ float g_g[8388608];
__device__ float g_h2[2097152];

// ---------------- helpers ----------------
__device__ __forceinline__ float block_reduce_sum(float v, float* sbuf) {
    int tid = threadIdx.x;
    sbuf[tid] = v; __syncthreads();
    for (int s = blockDim.x >> 1; s > 0; s >>= 1) {
        if (tid < s) sbuf[tid] += sbuf[tid + s];
        __syncthreads();
    }
    float r = sbuf[0]; __syncthreads();
    return r;
}
__device__ __forceinline__ float block_reduce_max(float v, float* sbuf) {
    int tid = threadIdx.x;
    sbuf[tid] = v; __syncthreads();
    for (int s = blockDim.x >> 1; s > 0; s >>= 1) {
        if (tid < s) sbuf[tid] = fmaxf(sbuf[tid], sbuf[tid + s]);
        __syncthreads();
    }
    float r = sbuf[0]; __syncthreads();
    return r;
}

// ======== bigM GEMM: C = (A@B^T + bias)*scale.  BM=128, TM=8, 256 thr ====
// A (M,K) row-major, B (N,K) row-major. M%128==0, N%BN==0, K%16==0.
template<int BN, int TNR>
__global__ void __launch_bounds__(256)
gemm_bigM_kernel(const float* __restrict__ A,
                 const float* __restrict__ B,
                 const float* __restrict__ bias,
                 float* __restrict__ C,
                 int N, int K, float scale)
{
    constexpr int BM = 128, BK = 16, TM = 8;
    __shared__ float As[2][BK][BM + 4];
    __shared__ float Bs[2][BK][BN + 4];
    int tid = threadIdx.x;
    int tx = tid & 15, ty = tid >> 4;
    int m0 = blockIdx.y * BM, n0 = blockIdx.x * BN;
    int ra = tid >> 2;            // 0..63
    int ca = (tid & 3) << 2;      // 0,4,8,12

    const float* Abase = A + (size_t)(m0 + ra) * K + ca;
    const float* Bbase = B + (size_t)(n0 + ra) * K + ca;

    float4 pa[2], pb[BN / 64];

    auto gload = [&](int k0) {
        pa[0] = *(const float4*)(Abase + k0);
        pa[1] = *(const float4*)(Abase + (size_t)64 * K + k0);
        #pragma unroll
        for (int u = 0; u < BN / 64; u++)
            pb[u] = *(const float4*)(Bbase + (size_t)(u * 64) * K + k0);
    };
    auto sstore = [&](int buf) {
        As[buf][ca + 0][ra] = pa[0].x; As[buf][ca + 1][ra] = pa[0].y;
        As[buf][ca + 2][ra] = pa[0].z; As[buf][ca + 3][ra] = pa[0].w;
        As[buf][ca + 0][ra + 64] = pa[1].x; As[buf][ca + 1][ra + 64] = pa[1].y;
        As[buf][ca + 2][ra + 64] = pa[1].z; As[buf][ca + 3][ra + 64] = pa[1].w;
        #pragma unroll
        for (int u = 0; u < BN / 64; u++) {
            Bs[buf][ca + 0][ra + u * 64] = pb[u].x;
            Bs[buf][ca + 1][ra + u * 64] = pb[u].y;
            Bs[buf][ca + 2][ra + u * 64] = pb[u].z;
            Bs[buf][ca + 3][ra + u * 64] = pb[u].w;
        }
    };

    float acc[TM][TNR] = {};
    gload(0); sstore(0); __syncthreads();
    int nk = K / BK;
    int buf = 0;
    for (int t = 0; t < nk; t++) {
        if (t + 1 < nk) gload((t + 1) * BK);
        #pragma unroll
        for (int kk = 0; kk < BK; kk++) {
            float a[TM], b[TNR];
            #pragma unroll
            for (int u = 0; u < TM / 4; u++)
                *(float4*)&a[u * 4] = *(const float4*)&As[buf][kk][ty * TM + u * 4];
            #pragma unroll
            for (int u = 0; u < TNR / 4; u++)
                *(float4*)&b[u * 4] = *(const float4*)&Bs[buf][kk][tx * TNR + u * 4];
            #pragma unroll
            for (int i = 0; i < TM; i++)
                #pragma unroll
                for (int j = 0; j < TNR; j++)
                    acc[i][j] += a[i] * b[j];
        }
        if (t + 1 < nk) { sstore(buf ^ 1); __syncthreads(); buf ^= 1; }
    }

    float bv[TNR];
    #pragma unroll
    for (int u = 0; u < TNR / 4; u++)
        *(float4*)&bv[u * 4] = *(const float4*)&bias[n0 + tx * TNR + u * 4];
    #pragma unroll
    for (int i = 0; i < TM; i++) {
        int m = m0 + ty * TM + i;
        #pragma unroll
        for (int u = 0; u < TNR / 4; u++) {
            float4 o;
            o.x = (acc[i][u * 4 + 0] + bv[u * 4 + 0]) * scale;
            o.y = (acc[i][u * 4 + 1] + bv[u * 4 + 1]) * scale;
            o.z = (acc[i][u * 4 + 2] + bv[u * 4 + 2]) * scale;
            o.w = (acc[i][u * 4 + 3] + bv[u * 4 + 3]) * scale;
            *(float4*)&C[(size_t)m * N + n0 + tx * TNR + u * 4] = o;
        }
    }
}

// ======== old generic 64x64 GEMM (kept for the tiny k/v projections) ====
#define OBM 64
#define OBN 64
#define OBK 16
__global__ void gemm_tb_kernel(const float* __restrict__ A,
                               const float* __restrict__ B,
                               const float* __restrict__ bias,
                               float* __restrict__ C,
                               int M, int N, int K, float scale)
{
    __shared__ float As[OBK][OBM];
    __shared__ float Bs[OBK][OBN];
    int tid = threadIdx.x;
    int tx = tid & 15, ty = tid >> 4;
    int m0 = blockIdx.y * OBM, n0 = blockIdx.x * OBN;
    float acc[4][4] = {};
    for (int k0 = 0; k0 < K; k0 += OBK) {
        #pragma unroll
        for (int j = 0; j < 4; j++) {
            int idx = tid + j * 256;
            int ml = idx / OBK, kl = idx % OBK;
            int m = m0 + ml, k = k0 + kl;
            As[kl][ml] = (m < M) ? A[(size_t)m * K + k] : 0.f;
        }
        #pragma unroll
        for (int j = 0; j < 4; j++) {
            int idx = tid + j * 256;
            int nl = idx / OBK, kl = idx % OBK;
            int n = n0 + nl, k = k0 + kl;
            Bs[kl][nl] = (n < N) ? B[(size_t)n * K + k] : 0.f;
        }
        __syncthreads();
        #pragma unroll
        for (int kk = 0; kk < OBK; kk++) {
            float a[4], b[4];
            *(float4*)a = *(const float4*)&As[kk][ty * 4];
            *(float4*)b = *(const float4*)&Bs[kk][tx * 4];
            #pragma unroll
            for (int i = 0; i < 4; i++)
                #pragma unroll
                for (int j = 0; j < 4; j++)
                    acc[i][j] += a[i] * b[j];
        }
        __syncthreads();
    }
    #pragma unroll
    for (int i = 0; i < 4; i++) {
        int m = m0 + ty * 4 + i;
        if (m >= M) continue;
        #pragma unroll
        for (int j = 0; j < 4; j++) {
            int n = n0 + tx * 4 + j;
            if (n >= N) continue;
            C[(size_t)m * N + n] = (acc[i][j] + bias[n]) * scale;
        }
    }
}

// ======== cl GEMM (NT, small M): cl[bt,k,n] = sum_c w[k,c]*xf[bt,n,c] ====
__global__ void __launch_bounds__(256)
cl_gemm2_kernel(const float* __restrict__ w,
                const float* __restrict__ x,
                const float* __restrict__ mem,
                float* __restrict__ cl)
{
    constexpr int BK = 16;
    int bt = blockIdx.z; int b = bt >> 2, t = bt & 3;
    const float* Bp = (t < 3) ? (mem + (size_t)(b * 3 + t) * N4 * CC)
                              : (x + (size_t)b * N4 * CC);
    float* Cp = cl + (size_t)bt * NC * N4;

    __shared__ float As[BK][68];
    __shared__ float Bs[BK][132];
    int tid = threadIdx.x;
    int tx = tid & 15, ty = tid >> 4;
    int m0 = blockIdx.y * 64, n0 = blockIdx.x * 128;
    int ra = tid >> 2, ca = (tid & 3) << 2;
    float acc[4][8] = {};
    for (int k0 = 0; k0 < CC; k0 += BK) {
        int mA = m0 + ra;
        float4 av = make_float4(0.f, 0.f, 0.f, 0.f);
        if (mA < NC) av = *(const float4*)(w + (size_t)mA * CC + k0 + ca);
        float4 bv0 = *(const float4*)(Bp + (size_t)(n0 + ra) * CC + k0 + ca);
        float4 bv1 = *(const float4*)(Bp + (size_t)(n0 + ra + 64) * CC + k0 + ca);
        __syncthreads();
        As[ca + 0][ra] = av.x; As[ca + 1][ra] = av.y;
        As[ca + 2][ra] = av.z; As[ca + 3][ra] = av.w;
        Bs[ca + 0][ra] = bv0.x; Bs[ca + 1][ra] = bv0.y;
        Bs[ca + 2][ra] = bv0.z; Bs[ca + 3][ra] = bv0.w;
        Bs[ca + 0][ra + 64] = bv1.x; Bs[ca + 1][ra + 64] = bv1.y;
        Bs[ca + 2][ra + 64] = bv1.z; Bs[ca + 3][ra + 64] = bv1.w;
        __syncthreads();
        #pragma unroll
        for (int kk = 0; kk < BK; kk++) {
            float a[4], b[8];
            *(float4*)&a[0] = *(const float4*)&As[kk][ty * 4];
            *(float4*)&b[0] = *(const float4*)&Bs[kk][tx * 8];
            *(float4*)&b[4] = *(const float4*)&Bs[kk][tx * 8 + 4];
            #pragma unroll
            for (int i = 0; i < 4; i++)
                #pragma unroll
                for (int j = 0; j < 8; j++)
                    acc[i][j] += a[i] * b[j];
        }
    }
    #pragma unroll
    for (int i = 0; i < 4; i++) {
        int m = m0 + ty * 4 + i;
        if (m >= NC) continue;
        *(float4*)&Cp[(size_t)m * N4 + n0 + tx * 8]     = *(float4*)&acc[i][0];
        *(float4*)&Cp[(size_t)m * N4 + n0 + tx * 8 + 4] = *(float4*)&acc[i][4];
    }
}

// ---- prompt scaling ----
__global__ void prompt_scale_kernel(const float* __restrict__ z,
                                    const float* __restrict__ cl,
                                    const float* __restrict__ p1,
                                    const float* __restrict__ p2,
                                    float* __restrict__ az,
                                    float* __restrict__ ac)
{
    int m = blockIdx.x * blockDim.x + threadIdx.x;
    int b = blockIdx.z;
    if (m >= TNE) return;
    int t = m / N4, n = m % N4;
    const float* zrow = z + (size_t)b * NC * TNE + m;
    const float* crow = cl + ((size_t)(b * TT4 + t) * NC) * N4 + n;
    float dz = 0, nz = 0, dc = 0, ncs = 0, p1n = 0, p2n = 0;
    for (int k = 0; k < NC; k++) {
        float zv = zrow[(size_t)k * TNE];
        float cv = crow[(size_t)k * N4];
        float a = p1[k], bb = p2[k];
        dz += zv * a; nz += zv * zv; p1n += a * a;
        dc += cv * bb; ncs += cv * cv; p2n += bb * bb;
    }
    float cz = dz / (fmaxf(sqrtf(nz), 1e-12f) * fmaxf(sqrtf(p1n), 1e-12f));
    cz = fminf(fmaxf(cz, 0.f), 1.f) * 0.5f;
    float cc = dc / (fmaxf(sqrtf(ncs), 1e-12f) * fmaxf(sqrtf(p2n), 1e-12f));
    cc = fminf(fmaxf(cc, 0.f), 1.f) * 0.5f;
    float* azp = az + (size_t)b * NC * TNE + m;
    float* acp = ac + (size_t)b * NC * TNE + m;
    for (int k = 0; k < NC; k++) {
        azp[(size_t)k * TNE] = cz * zrow[(size_t)k * TNE];
        acp[(size_t)k * TNE] = cc * crow[(size_t)k * N4];
    }
}

// ======== combine GEMM (NN, dual) + fused center write ====
__global__ void __launch_bounds__(256)
comb_gemm2_kernel(const float* __restrict__ tdt1,
                  const float* __restrict__ tdt2,
                  const float* __restrict__ az,
                  const float* __restrict__ ac,
                  float* __restrict__ cxz,
                  float* __restrict__ ctr)
{
    constexpr int BK = 16;
    int b = blockIdx.z;
    int j0 = blockIdx.y * 64, m0 = blockIdx.x * 128;
    __shared__ float As[BK][68];
    __shared__ float Bs[BK][132];
    int tid = threadIdx.x;
    int tx = tid & 15, ty = tid >> 4;
    int kr = tid >> 4;
    int jc = (tid & 15) << 2;
    int kb = tid >> 5;
    int mc = (tid & 31) << 2;
    float acc[4][8] = {};
    for (int s = 0; s < 2; s++) {
        const float* tdt = s ? tdt2 : tdt1;
        const float* bz = (s ? ac : az) + (size_t)b * NC * TNE;
        for (int k0 = 0; k0 < NC; k0 += BK) {
            int kA = k0 + kr;
            float a0 = 0, a1 = 0, a2 = 0, a3 = 0;
            if (kA < NC) {
                int j = j0 + jc;
                a0 = (j + 0 < NC) ? tdt[(size_t)kA * NC + j + 0] : 0.f;
                a1 = (j + 1 < NC) ? tdt[(size_t)kA * NC + j + 1] : 0.f;
                a2 = (j + 2 < NC) ? tdt[(size_t)kA * NC + j + 2] : 0.f;
                a3 = (j + 3 < NC) ? tdt[(size_t)kA * NC + j + 3] : 0.f;
            }
            int kB0 = k0 + kb, kB1 = k0 + kb + 8;
            float4 bv0 = make_float4(0.f, 0.f, 0.f, 0.f);
            float4 bv1 = make_float4(0.f, 0.f, 0.f, 0.f);
            if (kB0 < NC) bv0 = *(const float4*)(bz + (size_t)kB0 * TNE + m0 + mc);
            if (kB1 < NC) bv1 = *(const float4*)(bz + (size_t)kB1 * TNE + m0 + mc);
            __syncthreads();
            As[kr][jc + 0] = a0; As[kr][jc + 1] = a1;
            As[kr][jc + 2] = a2; As[kr][jc + 3] = a3;
            Bs[kb][mc + 0] = bv0.x; Bs[kb][mc + 1] = bv0.y;
            Bs[kb][mc + 2] = bv0.z; Bs[kb][mc + 3] = bv0.w;
            Bs[kb + 8][mc + 0] = bv1.x; Bs[kb + 8][mc + 1] = bv1.y;
            Bs[kb + 8][mc + 2] = bv1.z; Bs[kb + 8][mc + 3] = bv1.w;
            __syncthreads();
            #pragma unroll
            for (int kk = 0; kk < BK; kk++) {
                float a[4], bb[8];
                *(float4*)&a[0]  = *(const float4*)&As[kk][ty * 4];
                *(float4*)&bb[0] = *(const float4*)&Bs[kk][tx * 8];
                *(float4*)&bb[4] = *(const float4*)&Bs[kk][tx * 8 + 4];
                #pragma unroll
                for (int i = 0; i < 4; i++)
                    #pragma unroll
                    for (int j = 0; j < 8; j++)
                        acc[i][j] += a[i] * bb[j];
            }
        }
    }
    int t = m0 / N4;
    int n = (m0 & (N4 - 1)) + tx * 8;
    #pragma unroll
    for (int i = 0; i < 4; i++) {
        int jj = j0 + ty * 4 + i;
        if (jj >= NC) continue;
        float* cp = cxz + ((size_t)b * NC + jj) * TNE + m0 + tx * 8;
        *(float4*)cp       = *(float4*)&acc[i][0];
        *(float4*)(cp + 4) = *(float4*)&acc[i][4];
        float* tp = ctr + ((size_t)(b * TT4 + t) * NC + jj) * N4 + n;
        *(float4*)tp       = *(float4*)&acc[i][0];
        *(float4*)(tp + 4) = *(float4*)&acc[i][4];
    }
}

// ---- softmax over n per (b,t,k) row ----
__global__ void softmax_kernel(const float* __restrict__ cxz,
                               float* __restrict__ soft)
{
    __shared__ float sbuf[256];
    int r = blockIdx.x;
    int k = r % NC;
    int bt = r / NC;
    int b = bt / TT4, t = bt % TT4;
    const float* src = cxz + ((size_t)b * NC + k) * TNE + t * N4;
    float* dst = soft + (size_t)r * N4;
    int tid = threadIdx.x;
    float mx = -3.4e38f;
    for (int i = tid; i < N4; i += 256) mx = fmaxf(mx, src[i]);
    mx = block_reduce_max(mx, sbuf);
    float s = 0.f;
    for (int i = tid; i < N4; i += 256) {
        float e = expf(src[i] - mx);
        dst[i] = e;
        s += e;
    }
    s = block_reduce_sum(s, sbuf);
    float inv = 1.f / s;
    for (int i = tid; i < N4; i += 256) dst[i] *= inv;
}

// ---- zero cen ----
__global__ void zero_cen_kernel(float* __restrict__ cen)
{
    int i = blockIdx.x * blockDim.x + threadIdx.x;
    if (i < 307200) cen[i] = 0.f;
}

// ======== cen GEMM (NN, split-K, atomic) ====
__global__ void __launch_bounds__(256)
cen_gemm2_kernel(const float* __restrict__ soft,
                 const float* __restrict__ x,
                 const float* __restrict__ mem,
                 float* __restrict__ cen)
{
    constexpr int BK = 16;
    int bt = blockIdx.z >> 2, s = blockIdx.z & 3;
    int b = bt >> 2, t = bt & 3;
    const float* A = soft + (size_t)bt * NC * N4;
    const float* Bp = (t < 3) ? (mem + (size_t)(b * 3 + t) * N4 * CC)
                              : (x + (size_t)b * N4 * CC);
    float* Cp = cen + (size_t)bt * NC * CC;

    __shared__ float As[BK][68];
    __shared__ float Bs[BK][132];
    int tid = threadIdx.x;
    int tx = tid & 15, ty = tid >> 4;
    int m0 = blockIdx.y * 64, c0 = blockIdx.x * 128;
    int ra = tid >> 2, ca = (tid & 3) << 2;
    int kb = tid >> 5, cc = (tid & 31) << 2;
    float acc[4][8] = {};
    int kstart = s * 1024, kend = kstart + 1024;
    for (int k0 = kstart; k0 < kend; k0 += BK) {
        int mA = m0 + ra;
        float4 av = make_float4(0.f, 0.f, 0.f, 0.f);
        if (mA < NC) av = *(const float4*)(A + (size_t)mA * N4 + k0 + ca);
        float4 bv0 = *(const float4*)(Bp + (size_t)(k0 + kb) * CC + c0 + cc);
        float4 bv1 = *(const float4*)(Bp + (size_t)(k0 + kb + 8) * CC + c0 + cc);
        __syncthreads();
        As[ca + 0][ra] = av.x; As[ca + 1][ra] = av.y;
        As[ca + 2][ra] = av.z; As[ca + 3][ra] = av.w;
        Bs[kb][cc + 0] = bv0.x; Bs[kb][cc + 1] = bv0.y;
        Bs[kb][cc + 2] = bv0.z; Bs[kb][cc + 3] = bv0.w;
        Bs[kb + 8][cc + 0] = bv1.x; Bs[kb + 8][cc + 1] = bv1.y;
        Bs[kb + 8][cc + 2] = bv1.z; Bs[kb + 8][cc + 3] = bv1.w;
        __syncthreads();
        #pragma unroll
        for (int kk = 0; kk < BK; kk++) {
            float a[4], bb[8];
            *(float4*)&a[0]  = *(const float4*)&As[kk][ty * 4];
            *(float4*)&bb[0] = *(const float4*)&Bs[kk][tx * 8];
            *(float4*)&bb[4] = *(const float4*)&Bs[kk][tx * 8 + 4];
            #pragma unroll
            for (int i = 0; i < 4; i++)
                #pragma unroll
                for (int j = 0; j < 8; j++)
                    acc[i][j] += a[i] * bb[j];
        }
    }
    #pragma unroll
    for (int i = 0; i < 4; i++) {
        int m = m0 + ty * 4 + i;
        if (m >= NC) continue;
        #pragma unroll
        for (int j = 0; j < 8; j++)
            atomicAdd(&Cp[(size_t)m * CC + c0 + tx * 8 + j], acc[i][j]);
    }
}

// ---- C_in gating + LayerNorm ----
__global__ void cin_kernel(const float* __restrict__ cen,
                           const float* __restrict__ alpha,
                           const float* __restrict__ beta,
                           const float* __restrict__ nw,
                           const float* __restrict__ nb,
                           float* __restrict__ cinln)
{
    __shared__ float sbuf[256];
    int bk = blockIdx.x;
    int b = bk / NC, k = bk % NC;
    int c = threadIdx.x;
    float last = cen[((size_t)(b * TT4 + 3) * NC + k) * CC + c];
    float pv[3];
    #pragma unroll
    for (int t = 0; t < 3; t++)
        pv[t] = cen[((size_t)(b * TT4 + t) * NC + k) * CC + c];
    float nl = block_reduce_sum(last * last, sbuf);
    float al = alpha[0], be = beta[0];
    float g[3];
    #pragma unroll
    for (int t = 0; t < 3; t++) {
        float dt = block_reduce_sum(last * pv[t], sbuf);
        float np = block_reduce_sum(pv[t] * pv[t], sbuf);
        float denom = fmaxf(sqrtf(nl) * sqrtf(np), 1e-8f);
        g[t] = 1.f / (1.f + expf(-(be + al * dt / denom)));
    }
    float cin = last + g[0] * pv[0] + g[1] * pv[1] + g[2] * pv[2];
    float mean = block_reduce_sum(cin, sbuf) * (1.f / CC);
    float d = cin - mean;
    float var = block_reduce_sum(d * d, sbuf) * (1.f / CC);
    cinln[((size_t)b * NC + k) * CC + c] = d * rsqrtf(var + 1e-5f) * nw[c] + nb[c];
}

// ---- attention ----
__global__ void attn_kernel(const float* __restrict__ q,
                            const float* __restrict__ kbuf,
                            const float* __restrict__ vbuf,
                            float* __restrict__ o)
{
    __shared__ float kh[NC * 33];
    __shared__ float vh[NC * 33];
    int b = blockIdx.z, h = blockIdx.y;
    int tid = threadIdx.x;
    int warp = tid >> 5, lane = tid & 31;
    for (int idx = tid; idx < NC * HD; idx += blockDim.x) {
        int kk = idx / HD, d = idx % HD;
        kh[kk * 33 + d] = kbuf[((size_t)b * NC + kk) * CC + h * HD + d];
        vh[kk * 33 + d] = vbuf[((size_t)b * NC + kk) * CC + h * HD + d];
    }
    __syncthreads();
    const unsigned FULL = 0xffffffffu;
    for (int ni = warp; ni < 256; ni += 8) {
        int n = blockIdx.x * 256 + ni;
        float qv = q[((size_t)b * N4 + n) * CC + h * HD + lane];
        float lg[5];
        #pragma unroll
        for (int i = 0; i < 5; i++) {
            int kk = lane + 32 * i;
            int kks = (kk < NC) ? kk : (NC - 1);
            float acc = 0.f;
            #pragma unroll
            for (int d = 0; d < 32; d++) {
                float qd = __shfl_sync(FULL, qv, d);
                acc += qd * kh[kks * 33 + d];
            }
            lg[i] = (kk < NC) ? acc : -3.4e38f;
        }
        float mx = lg[0];
        #pragma unroll
        for (int i = 1; i < 5; i++) mx = fmaxf(mx, lg[i]);
        #pragma unroll
        for (int off = 16; off > 0; off >>= 1)
            mx = fmaxf(mx, __shfl_xor_sync(FULL, mx, off));
        float p[5], s = 0.f;
        #pragma unroll
        for (int i = 0; i < 5; i++) { p[i] = expf(lg[i] - mx); s += p[i]; }
        #pragma unroll
        for (int off = 16; off > 0; off >>= 1)
            s += __shfl_xor_sync(FULL, s, off);
        float inv = 1.f / s;
        float od = 0.f;
        #pragma unroll
        for (int i = 0; i < 5; i++) {
            float pi = p[i] * inv;
            #pragma unroll
            for (int l = 0; l < 32; l++) {
                float a = __shfl_sync(FULL, pi, l);
                int kk = l + 32 * i;
                if (kk < NC) od += a * vh[kk * 33 + lane];
            }
        }
        o[((size_t)b * N4 + n) * CC + h * HD + lane] = od;
    }
}

// ---- out = base + LayerNorm(xin) ----
__global__ void ln_add_kernel(const float* __restrict__ base,
                              const float* __restrict__ xin,
                              const float* __restrict__ nw,
                              const float* __restrict__ nb,
                              float* __restrict__ out)
{
    __shared__ float sbuf[256];
    size_t row = blockIdx.x;
    int c = threadIdx.x;
    float v = xin[row * CC + c];
    float mean = block_reduce_sum(v, sbuf) * (1.f / CC);
    float d = v - mean;
    float var = block_reduce_sum(d * d, sbuf) * (1.f / CC);
    out[row * CC + c] = base[row * CC + c] + d * rsqrtf(var + 1e-5f) * nw[c] + nb[c];
}

// ---- depthwise 3x3 SAME conv + bias + exact GELU ----
__global__ void dwconv_gelu_kernel(const float* __restrict__ h1,
                                   const float* __restrict__ dw_w,
                                   const float* __restrict__ dw_b,
                                   float* __restrict__ g)
{
    int idx = blockIdx.x * blockDim.x + threadIdx.x;
    if (idx >= BB * N4 * HID) return;
    int ch = idx & (HID - 1);
    int r = idx >> 10;
    int n = r & (N4 - 1);
    int b = r >> 12;
    int y = n >> 6, x = n & 63;
    float acc = dw_b[ch];
    #pragma unroll
    for (int dy = 0; dy < 3; dy++) {
        int yy = y + dy - 1;
        if (yy < 0 || yy >= HH) continue;
        #pragma unroll
        for (int dx = 0; dx < 3; dx++) {
            int xx = x + dx - 1;
            if (xx < 0 || xx >= WW) continue;
            acc += h1[((size_t)b * N4 + yy * WW + xx) * HID + ch] *
                   dw_w[ch * 9 + dy * 3 + dx];
        }
    }
    g[idx] = 0.5f * acc * (1.0f + erff(acc * 0.70710678118654752f));
}

// ================= host launcher =================
extern "C" void kernel_launch(void* const* d_in, const int* in_sizes, int n_in,
                              void* d_out, int out_size)
{
    const float* x      = (const float*)d_in[0];
    const float* z      = (const float*)d_in[1];
    const float* mem    = (const float*)d_in[2];
    const float* cw     = (const float*)d_in[3];
    const float* p1     = (const float*)d_in[4];
    const float* tdt1   = (const float*)d_in[5];
    const float* p2     = (const float*)d_in[6];
    const float* tdt2   = (const float*)d_in[7];
    const float* alpha  = (const float*)d_in[8];
    const float* beta   = (const float*)d_in[9];
    const float* q_w    = (const float*)d_in[10];
    const float* q_b    = (const float*)d_in[11];
    const float* k_w    = (const float*)d_in[12];
    const float* k_b    = (const float*)d_in[13];
    const float* v_w    = (const float*)d_in[14];
    const float* v_b    = (const float*)d_in[15];
    const float* proj_w = (const float*)d_in[16];
    const float* proj_b = (const float*)d_in[17];
    const float* norm_w = (const float*)d_in[18];
    const float* norm_b = (const float*)d_in[19];
    const float* fc1_w  = (const float*)d_in[20];
    const float* fc1_b  = (const float*)d_in[21];
    const float* dw_w   = (const float*)d_in[22];
    const float* dw_b   = (const float*)d_in[23];
    const float* fc2_w  = (const float*)d_in[24];
    const float* fc2_b  = (const float*)d_in[25];

    float* out0 = (float*)d_out;
    float* cxz  = out0 + OUT0_ELEMS;
    float* ctr  = out0 + OUT0_ELEMS + CXZ_ELEMS;

    float *cl, *az, *ac, *soft, *cen, *cinln, *kb, *vb, *qb, *ob, *oproj,
          *out1, *h1, *gg, *h2;
    cudaGetSymbolAddress((void**)&cl,    g_cl);
    cudaGetSymbolAddress((void**)&az,    g_az);
    cudaGetSymbolAddress((void**)&ac,    g_ac);
    cudaGetSymbolAddress((void**)&soft,  g_soft);
    cudaGetSymbolAddress((void**)&cen,   g_cen);
    cudaGetSymbolAddress((void**)&cinln, g_cinln);
    cudaGetSymbolAddress((void**)&kb,    g_kbuf);
    cudaGetSymbolAddress((void**)&vb,    g_vbuf);
    cudaGetSymbolAddress((void**)&qb,    g_q);
    cudaGetSymbolAddress((void**)&ob,    g_o);
    cudaGetSymbolAddress((void**)&oproj, g_oproj);
    cudaGetSymbolAddress((void**)&out1,  g_out1);
    cudaGetSymbolAddress((void**)&h1,    g_h1);
    cudaGetSymbolAddress((void**)&gg,    g_g);
    cudaGetSymbolAddress((void**)&h2,    g_h2);

    // 1) cl
    cl_gemm2_kernel<<<dim3(N4 / 128, 3, BB * TT4), 256>>>(cw, x, mem, cl);
    // 2) prompt cos + scaling
    prompt_scale_kernel<<<dim3(TNE / 256, 1, BB), 256>>>(z, cl, p1, p2, az, ac);
    // 3) combine GEMM -> cluster_x_z + center (outputs #2, #3)
    comb_gemm2_kernel<<<dim3(TNE / 128, 3, BB), 256>>>(tdt1, tdt2, az, ac, cxz, ctr);
    // 4) softmax
    softmax_kernel<<<BB * TT4 * NC, 256>>>(cxz, soft);
    // 5) cen (split-K, atomic)
    zero_cen_kernel<<<(307200 + 255) / 256, 256>>>(cen);
    cen_gemm2_kernel<<<dim3(CC / 128, 3, BB * TT4 * 4), 256>>>(soft, x, mem, cen);
    // 6) gating + LN
    cin_kernel<<<BB * NC, 256>>>(cen, alpha, beta, norm_w, norm_b, cinln);
    // 7) k/v projections (tiny)
    gemm_tb_kernel<<<dim3(CC / OBN, (BB * NC + OBM - 1) / OBM), 256>>>(
        cinln, k_w, k_b, kb, BB * NC, CC, CC, 1.f);
    gemm_tb_kernel<<<dim3(CC / OBN, (BB * NC + OBM - 1) / OBM), 256>>>(
        cinln, v_w, v_b, vb, BB * NC, CC, CC, 1.f);
    // 8) q projection
    gemm_bigM_kernel<64, 4><<<dim3(CC / 64, BB * N4 / 128), 256>>>(
        x, q_w, q_b, qb, CC, CC, 0.17677669529663687f);
    // 9) attention
    attn_kernel<<<dim3(N4 / 256, NH, BB), 256>>>(qb, kb, vb, ob);
    // 10) output projection
    gemm_bigM_kernel<64, 4><<<dim3(CC / 64, BB * N4 / 128), 256>>>(
        ob, proj_w, proj_b, oproj, CC, CC, 1.f);
    // 11) out1 = x + LN(oproj)
    ln_add_kernel<<<BB * N4, 256>>>(x, oproj, norm_w, norm_b, out1);
    // 12) fc1
    gemm_bigM_kernel<128, 8><<<dim3(HID / 128, BB * N4 / 128), 256>>>(
        out1, fc1_w, fc1_b, h1, HID, CC, 1.f);
    // 13) depthwise conv + gelu
    dwconv_gelu_kernel<<<(BB * N4 * HID + 255) / 256, 256>>>(h1, dw_w, dw_b, gg);
    // 14) fc2
    gemm_bigM_kernel<64, 4><<<dim3(CC / 64, BB * N4 / 128), 256>>>(
        gg, fc2_w, fc2_b, h2, CC, HID, 1.f);
    // 15) out = out1 + LN(h2)
    ln_add_kernel<<<BB * N4, 256>>>(out1, h2, norm_w, norm_b, out0);
}

// round 5
// speedup vs baseline: 1.5633x; 1.0852x over previous
#include <cuda_runtime.h>
#include <cuda_bf16.h>
#include <math.h>
#include <stdint.h>

// ---------------- fixed problem dims ----------------
#define BB   2
#define TT4  4
#define N4   4096
#define CC   256
#define NC   150
#define TNE  16384
#define HID  1024
#define NH   8
#define HD   32
#define HH   64
#define WW   64

#define OUT0_ELEMS 2097152
#define CXZ_ELEMS  4915200

// ---------------- scratch ----------------
__device__ float g_cl[4915200];
__device__ float g_az[4915200];
__device__ float g_ac[4915200];
__device__ float g_soft[4915200];
__device__ float g_cen[307200];
__device__ float g_cinln[76800];
__device__ float g_kbuf[76800];
__device__ float g_vbuf[76800];
__device__ float g_q[2097152];
__device__ float g_o[2097152];
__device__ float g_oproj[2097152];
__device__ float g_out1[2097152];
__device__ float g_h1[8388608];
__device__ float g_h2[2097152];

// bf16 hi/lo split buffers
__device__ __nv_bfloat16 g_xh[2097152],  g_xl[2097152];
__device__ __nv_bfloat16 g_obh[2097152], g_obl[2097152];
__device__ __nv_bfloat16 g_o1h[2097152], g_o1l[2097152];
__device__ __nv_bfloat16 g_gh[8388608],  g_gl[8388608];
__device__ __nv_bfloat16 g_qwh[65536],  g_qwl[65536];
__device__ __nv_bfloat16 g_pwh[65536],  g_pwl[65536];
__device__ __nv_bfloat16 g_f1h[262144], g_f1l[262144];
__device__ __nv_bfloat16 g_f2h[262144], g_f2l[262144];

// ---------------- warp-level bf16 MMA (base ISA, no tcgen05) ----------
__device__ __forceinline__ void mma16816(float* d, const uint32_t* a, const uint32_t* b) {
    asm volatile(
        "mma.sync.aligned.m16n8k16.row.col.f32.bf16.bf16.f32 "
        "{%0,%1,%2,%3}, {%4,%5,%6,%7}, {%8,%9}, {%0,%1,%2,%3};\n"
        : "+f"(d[0]), "+f"(d[1]), "+f"(d[2]), "+f"(d[3])
        : "r"(a[0]), "r"(a[1]), "r"(a[2]), "r"(a[3]), "r"(b[0]), "r"(b[1]));
}

// ================= HMMA bf16-split GEMM =================
// C[M,Ntot] = ((Ah+Al) @ (Bh+Bl)^T + bias) * scale, 3-term split, fp32 accum.
// Block tile 128x128, 8 warps (each 32x64), K-chunk 32.
// A (M,K) row-major bf16 pair; B (Ntot,K) row-major bf16 pair.
#define SAS 40   // smem row stride in bf16 elems
__global__ void __launch_bounds__(256)
hmma_gemm_kernel(const __nv_bfloat16* __restrict__ Ah, const __nv_bfloat16* __restrict__ Al,
                 const __nv_bfloat16* __restrict__ Bh, const __nv_bfloat16* __restrict__ Bl,
                 const float* __restrict__ bias, float* __restrict__ C,
                 int Ntot, int K, float scale)
{
    __shared__ __nv_bfloat16 sAh[128][SAS], sAl[128][SAS];
    __shared__ __nv_bfloat16 sBh[128][SAS], sBl[128][SAS];

    int tid = threadIdx.x, wid = tid >> 5, lane = tid & 31;
    int wm = wid & 3, wn = wid >> 2;          // warp tile: rows wm*32, cols wn*64
    int g = lane >> 2, tg = lane & 3;
    int m0 = blockIdx.y * 128, n0 = blockIdx.x * 128;

    int lrow = tid >> 1;            // 0..127
    int lhalf = (tid & 1) * 16;     // 0 or 16

    float acc[2][8][4];
    #pragma unroll
    for (int i = 0; i < 2; i++)
        #pragma unroll
        for (int j = 0; j < 8; j++)
            #pragma unroll
            for (int k = 0; k < 4; k++) acc[i][j][k] = 0.f;

    for (int k0 = 0; k0 < K; k0 += 32) {
        // stage K-chunk into SMEM (each thread: 16 bf16 per tile = 2 x uint4)
        const __nv_bfloat16* pa_h = Ah + (size_t)(m0 + lrow) * K + k0 + lhalf;
        const __nv_bfloat16* pa_l = Al + (size_t)(m0 + lrow) * K + k0 + lhalf;
        const __nv_bfloat16* pb_h = Bh + (size_t)(n0 + lrow) * K + k0 + lhalf;
        const __nv_bfloat16* pb_l = Bl + (size_t)(n0 + lrow) * K + k0 + lhalf;
        __syncthreads();
        *(uint4*)&sAh[lrow][lhalf]     = *(const uint4*)(pa_h);
        *(uint4*)&sAh[lrow][lhalf + 8] = *(const uint4*)(pa_h + 8);
        *(uint4*)&sAl[lrow][lhalf]     = *(const uint4*)(pa_l);
        *(uint4*)&sAl[lrow][lhalf + 8] = *(const uint4*)(pa_l + 8);
        *(uint4*)&sBh[lrow][lhalf]     = *(const uint4*)(pb_h);
        *(uint4*)&sBh[lrow][lhalf + 8] = *(const uint4*)(pb_h + 8);
        *(uint4*)&sBl[lrow][lhalf]     = *(const uint4*)(pb_l);
        *(uint4*)&sBl[lrow][lhalf + 8] = *(const uint4*)(pb_l + 8);
        __syncthreads();

        #pragma unroll
        for (int ks = 0; ks < 2; ks++) {
            int kc = ks * 16 + tg * 2;
            uint32_t ah[2][4], al[2][4], bh[8][2], bl[8][2];
            #pragma unroll
            for (int mt = 0; mt < 2; mt++) {
                int r = wm * 32 + mt * 16 + g;
                ah[mt][0] = *(const uint32_t*)&sAh[r][kc];
                ah[mt][1] = *(const uint32_t*)&sAh[r + 8][kc];
                ah[mt][2] = *(const uint32_t*)&sAh[r][kc + 8];
                ah[mt][3] = *(const uint32_t*)&sAh[r + 8][kc + 8];
                al[mt][0] = *(const uint32_t*)&sAl[r][kc];
                al[mt][1] = *(const uint32_t*)&sAl[r + 8][kc];
                al[mt][2] = *(const uint32_t*)&sAl[r][kc + 8];
                al[mt][3] = *(const uint32_t*)&sAl[r + 8][kc + 8];
            }
            #pragma unroll
            for (int nt = 0; nt < 8; nt++) {
                int nr = wn * 64 + nt * 8 + g;
                bh[nt][0] = *(const uint32_t*)&sBh[nr][kc];
                bh[nt][1] = *(const uint32_t*)&sBh[nr][kc + 8];
                bl[nt][0] = *(const uint32_t*)&sBl[nr][kc];
                bl[nt][1] = *(const uint32_t*)&sBl[nr][kc + 8];
            }
            #pragma unroll
            for (int mt = 0; mt < 2; mt++)
                #pragma unroll
                for (int nt = 0; nt < 8; nt++) {
                    mma16816(acc[mt][nt], ah[mt], bh[nt]);
                    mma16816(acc[mt][nt], ah[mt], bl[nt]);
                    mma16816(acc[mt][nt], al[mt], bh[nt]);
                }
        }
    }

    // epilogue: direct float2 stores with bias+scale
    #pragma unroll
    for (int mt = 0; mt < 2; mt++) {
        int r0 = m0 + wm * 32 + mt * 16 + g;
        #pragma unroll
        for (int nt = 0; nt < 8; nt++) {
            int col = n0 + wn * 64 + nt * 8 + tg * 2;
            float b0 = bias[col], b1 = bias[col + 1];
            float2 v0, v1;
            v0.x = (acc[mt][nt][0] + b0) * scale;
            v0.y = (acc[mt][nt][1] + b1) * scale;
            v1.x = (acc[mt][nt][2] + b0) * scale;
            v1.y = (acc[mt][nt][3] + b1) * scale;
            *(float2*)&C[(size_t)r0 * Ntot + col] = v0;
            *(float2*)&C[(size_t)(r0 + 8) * Ntot + col] = v1;
        }
    }
}

// ---------------- fp32 -> bf16 hi/lo split ----------------
__global__ void cvt_split_kernel(const float* __restrict__ in,
                                 __nv_bfloat16* __restrict__ hi,
                                 __nv_bfloat16* __restrict__ lo, int n)
{
    int i = (blockIdx.x * blockDim.x + threadIdx.x) * 4;
    if (i >= n) return;
    float4 v = *(const float4*)(in + i);
    __nv_bfloat16 h0 = __float2bfloat16(v.x), h1 = __float2bfloat16(v.y);
    __nv_bfloat16 h2 = __float2bfloat16(v.z), h3 = __float2bfloat16(v.w);
    __nv_bfloat16 l0 = __float2bfloat16(v.x - __bfloat162float(h0));
    __nv_bfloat16 l1 = __float2bfloat16(v.y - __bfloat162float(h1));
    __nv_bfloat16 l2 = __float2bfloat16(v.z - __bfloat162float(h2));
    __nv_bfloat16 l3 = __float2bfloat16(v.w - __bfloat162float(h3));
    *(__nv_bfloat162*)(hi + i)     = __nv_bfloat162(h0, h1);
    *(__nv_bfloat162*)(hi + i + 2) = __nv_bfloat162(h2, h3);
    *(__nv_bfloat162*)(lo + i)     = __nv_bfloat162(l0, l1);
    *(__nv_bfloat162*)(lo + i + 2) = __nv_bfloat162(l2, l3);
}

// ---------------- helpers ----------------
__device__ __forceinline__ float block_reduce_sum(float v, float* sbuf) {
    int tid = threadIdx.x;
    sbuf[tid] = v; __syncthreads();
    for (int s = blockDim.x >> 1; s > 0; s >>= 1) {
        if (tid < s) sbuf[tid] += sbuf[tid + s];
        __syncthreads();
    }
    float r = sbuf[0]; __syncthreads();
    return r;
}
__device__ __forceinline__ float block_reduce_max(float v, float* sbuf) {
    int tid = threadIdx.x;
    sbuf[tid] = v; __syncthreads();
    for (int s = blockDim.x >> 1; s > 0; s >>= 1) {
        if (tid < s) sbuf[tid] = fmaxf(sbuf[tid], sbuf[tid + s]);
        __syncthreads();
    }
    float r = sbuf[0]; __syncthreads();
    return r;
}

// ======== generic 64x64 GEMM (tiny k/v projections) ====
#define OBM 64
#define OBN 64
#define OBK 16
__global__ void gemm_tb_kernel(const float* __restrict__ A,
                               const float* __restrict__ B,
                               const float* __restrict__ bias,
                               float* __restrict__ C,
                               int M, int N, int K, float scale)
{
    __shared__ float As[OBK][OBM];
    __shared__ float Bs[OBK][OBN];
    int tid = threadIdx.x;
    int tx = tid & 15, ty = tid >> 4;
    int m0 = blockIdx.y * OBM, n0 = blockIdx.x * OBN;
    float acc[4][4] = {};
    for (int k0 = 0; k0 < K; k0 += OBK) {
        #pragma unroll
        for (int j = 0; j < 4; j++) {
            int idx = tid + j * 256;
            int ml = idx / OBK, kl = idx % OBK;
            int m = m0 + ml, k = k0 + kl;
            As[kl][ml] = (m < M) ? A[(size_t)m * K + k] : 0.f;
        }
        #pragma unroll
        for (int j = 0; j < 4; j++) {
            int idx = tid + j * 256;
            int nl = idx / OBK, kl = idx % OBK;
            int n = n0 + nl, k = k0 + kl;
            Bs[kl][nl] = (n < N) ? B[(size_t)n * K + k] : 0.f;
        }
        __syncthreads();
        #pragma unroll
        for (int kk = 0; kk < OBK; kk++) {
            float a[4], b[4];
            *(float4*)a = *(const float4*)&As[kk][ty * 4];
            *(float4*)b = *(const float4*)&Bs[kk][tx * 4];
            #pragma unroll
            for (int i = 0; i < 4; i++)
                #pragma unroll
                for (int j = 0; j < 4; j++)
                    acc[i][j] += a[i] * b[j];
        }
        __syncthreads();
    }
    #pragma unroll
    for (int i = 0; i < 4; i++) {
        int m = m0 + ty * 4 + i;
        if (m >= M) continue;
        #pragma unroll
        for (int j = 0; j < 4; j++) {
            int n = n0 + tx * 4 + j;
            if (n >= N) continue;
            C[(size_t)m * N + n] = (acc[i][j] + bias[n]) * scale;
        }
    }
}

// ======== cl GEMM ====
__global__ void __launch_bounds__(256)
cl_gemm2_kernel(const float* __restrict__ w,
                const float* __restrict__ x,
                const float* __restrict__ mem,
                float* __restrict__ cl)
{
    constexpr int BK = 16;
    int bt = blockIdx.z; int b = bt >> 2, t = bt & 3;
    const float* Bp = (t < 3) ? (mem + (size_t)(b * 3 + t) * N4 * CC)
                              : (x + (size_t)b * N4 * CC);
    float* Cp = cl + (size_t)bt * NC * N4;

    __shared__ float As[BK][68];
    __shared__ float Bs[BK][132];
    int tid = threadIdx.x;
    int tx = tid & 15, ty = tid >> 4;
    int m0 = blockIdx.y * 64, n0 = blockIdx.x * 128;
    int ra = tid >> 2, ca = (tid & 3) << 2;
    float acc[4][8] = {};
    for (int k0 = 0; k0 < CC; k0 += BK) {
        int mA = m0 + ra;
        float4 av = make_float4(0.f, 0.f, 0.f, 0.f);
        if (mA < NC) av = *(const float4*)(w + (size_t)mA * CC + k0 + ca);
        float4 bv0 = *(const float4*)(Bp + (size_t)(n0 + ra) * CC + k0 + ca);
        float4 bv1 = *(const float4*)(Bp + (size_t)(n0 + ra + 64) * CC + k0 + ca);
        __syncthreads();
        As[ca + 0][ra] = av.x; As[ca + 1][ra] = av.y;
        As[ca + 2][ra] = av.z; As[ca + 3][ra] = av.w;
        Bs[ca + 0][ra] = bv0.x; Bs[ca + 1][ra] = bv0.y;
        Bs[ca + 2][ra] = bv0.z; Bs[ca + 3][ra] = bv0.w;
        Bs[ca + 0][ra + 64] = bv1.x; Bs[ca + 1][ra + 64] = bv1.y;
        Bs[ca + 2][ra + 64] = bv1.z; Bs[ca + 3][ra + 64] = bv1.w;
        __syncthreads();
        #pragma unroll
        for (int kk = 0; kk < BK; kk++) {
            float a[4], b[8];
            *(float4*)&a[0] = *(const float4*)&As[kk][ty * 4];
            *(float4*)&b[0] = *(const float4*)&Bs[kk][tx * 8];
            *(float4*)&b[4] = *(const float4*)&Bs[kk][tx * 8 + 4];
            #pragma unroll
            for (int i = 0; i < 4; i++)
                #pragma unroll
                for (int j = 0; j < 8; j++)
                    acc[i][j] += a[i] * b[j];
        }
    }
    #pragma unroll
    for (int i = 0; i < 4; i++) {
        int m = m0 + ty * 4 + i;
        if (m >= NC) continue;
        *(float4*)&Cp[(size_t)m * N4 + n0 + tx * 8]     = *(float4*)&acc[i][0];
        *(float4*)&Cp[(size_t)m * N4 + n0 + tx * 8 + 4] = *(float4*)&acc[i][4];
    }
}

// ---- prompt scaling ----
__global__ void prompt_scale_kernel(const float* __restrict__ z,
                                    const float* __restrict__ cl,
                                    const float* __restrict__ p1,
                                    const float* __restrict__ p2,
                                    float* __restrict__ az,
                                    float* __restrict__ ac)
{
    int m = blockIdx.x * blockDim.x + threadIdx.x;
    int b = blockIdx.z;
    if (m >= TNE) return;
    int t = m / N4, n = m % N4;
    const float* zrow = z + (size_t)b * NC * TNE + m;
    const float* crow = cl + ((size_t)(b * TT4 + t) * NC) * N4 + n;
    float dz = 0, nz = 0, dc = 0, ncs = 0, p1n = 0, p2n = 0;
    for (int k = 0; k < NC; k++) {
        float zv = zrow[(size_t)k * TNE];
        float cv = crow[(size_t)k * N4];
        float a = p1[k], bb = p2[k];
        dz += zv * a; nz += zv * zv; p1n += a * a;
        dc += cv * bb; ncs += cv * cv; p2n += bb * bb;
    }
    float cz = dz / (fmaxf(sqrtf(nz), 1e-12f) * fmaxf(sqrtf(p1n), 1e-12f));
    cz = fminf(fmaxf(cz, 0.f), 1.f) * 0.5f;
    float cc = dc / (fmaxf(sqrtf(ncs), 1e-12f) * fmaxf(sqrtf(p2n), 1e-12f));
    cc = fminf(fmaxf(cc, 0.f), 1.f) * 0.5f;
    float* azp = az + (size_t)b * NC * TNE + m;
    float* acp = ac + (size_t)b * NC * TNE + m;
    for (int k = 0; k < NC; k++) {
        azp[(size_t)k * TNE] = cz * zrow[(size_t)k * TNE];
        acp[(size_t)k * TNE] = cc * crow[(size_t)k * N4];
    }
}

// ======== combine GEMM + fused center write ====
__global__ void __launch_bounds__(256)
comb_gemm2_kernel(const float* __restrict__ tdt1,
                  const float* __restrict__ tdt2,
                  const float* __restrict__ az,
                  const float* __restrict__ ac,
                  float* __restrict__ cxz,
                  float* __restrict__ ctr)
{
    constexpr int BK = 16;
    int b = blockIdx.z;
    int j0 = blockIdx.y * 64, m0 = blockIdx.x * 128;
    __shared__ float As[BK][68];
    __shared__ float Bs[BK][132];
    int tid = threadIdx.x;
    int tx = tid & 15, ty = tid >> 4;
    int kr = tid >> 4;
    int jc = (tid & 15) << 2;
    int kb = tid >> 5;
    int mc = (tid & 31) << 2;
    float acc[4][8] = {};
    for (int s = 0; s < 2; s++) {
        const float* tdt = s ? tdt2 : tdt1;
        const float* bz = (s ? ac : az) + (size_t)b * NC * TNE;
        for (int k0 = 0; k0 < NC; k0 += BK) {
            int kA = k0 + kr;
            float a0 = 0, a1 = 0, a2 = 0, a3 = 0;
            if (kA < NC) {
                int j = j0 + jc;
                a0 = (j + 0 < NC) ? tdt[(size_t)kA * NC + j + 0] : 0.f;
                a1 = (j + 1 < NC) ? tdt[(size_t)kA * NC + j + 1] : 0.f;
                a2 = (j + 2 < NC) ? tdt[(size_t)kA * NC + j + 2] : 0.f;
                a3 = (j + 3 < NC) ? tdt[(size_t)kA * NC + j + 3] : 0.f;
            }
            int kB0 = k0 + kb, kB1 = k0 + kb + 8;
            float4 bv0 = make_float4(0.f, 0.f, 0.f, 0.f);
            float4 bv1 = make_float4(0.f, 0.f, 0.f, 0.f);
            if (kB0 < NC) bv0 = *(const float4*)(bz + (size_t)kB0 * TNE + m0 + mc);
            if (kB1 < NC) bv1 = *(const float4*)(bz + (size_t)kB1 * TNE + m0 + mc);
            __syncthreads();
            As[kr][jc + 0] = a0; As[kr][jc + 1] = a1;
            As[kr][jc + 2] = a2; As[kr][jc + 3] = a3;
            Bs[kb][mc + 0] = bv0.x; Bs[kb][mc + 1] = bv0.y;
            Bs[kb][mc + 2] = bv0.z; Bs[kb][mc + 3] = bv0.w;
            Bs[kb + 8][mc + 0] = bv1.x; Bs[kb + 8][mc + 1] = bv1.y;
            Bs[kb + 8][mc + 2] = bv1.z; Bs[kb + 8][mc + 3] = bv1.w;
            __syncthreads();
            #pragma unroll
            for (int kk = 0; kk < BK; kk++) {
                float a[4], bb[8];
                *(float4*)&a[0]  = *(const float4*)&As[kk][ty * 4];
                *(float4*)&bb[0] = *(const float4*)&Bs[kk][tx * 8];
                *(float4*)&bb[4] = *(const float4*)&Bs[kk][tx * 8 + 4];
                #pragma unroll
                for (int i = 0; i < 4; i++)
                    #pragma unroll
                    for (int j = 0; j < 8; j++)
                        acc[i][j] += a[i] * bb[j];
            }
        }
    }
    int t = m0 / N4;
    int n = (m0 & (N4 - 1)) + tx * 8;
    #pragma unroll
    for (int i = 0; i < 4; i++) {
        int jj = j0 + ty * 4 + i;
        if (jj >= NC) continue;
        float* cp = cxz + ((size_t)b * NC + jj) * TNE + m0 + tx * 8;
        *(float4*)cp       = *(float4*)&acc[i][0];
        *(float4*)(cp + 4) = *(float4*)&acc[i][4];
        float* tp = ctr + ((size_t)(b * TT4 + t) * NC + jj) * N4 + n;
        *(float4*)tp       = *(float4*)&acc[i][0];
        *(float4*)(tp + 4) = *(float4*)&acc[i][4];
    }
}

// ---- softmax ----
__global__ void softmax_kernel(const float* __restrict__ cxz,
                               float* __restrict__ soft)
{
    __shared__ float sbuf[256];
    int r = blockIdx.x;
    int k = r % NC;
    int bt = r / NC;
    int b = bt / TT4, t = bt % TT4;
    const float* src = cxz + ((size_t)b * NC + k) * TNE + t * N4;
    float* dst = soft + (size_t)r * N4;
    int tid = threadIdx.x;
    float mx = -3.4e38f;
    for (int i = tid; i < N4; i += 256) mx = fmaxf(mx, src[i]);
    mx = block_reduce_max(mx, sbuf);
    float s = 0.f;
    for (int i = tid; i < N4; i += 256) {
        float e = expf(src[i] - mx);
        dst[i] = e;
        s += e;
    }
    s = block_reduce_sum(s, sbuf);
    float inv = 1.f / s;
    for (int i = tid; i < N4; i += 256) dst[i] *= inv;
}

// ---- zero cen ----
__global__ void zero_cen_kernel(float* __restrict__ cen)
{
    int i = blockIdx.x * blockDim.x + threadIdx.x;
    if (i < 307200) cen[i] = 0.f;
}

// ======== cen GEMM (split-K, atomic) ====
__global__ void __launch_bounds__(256)
cen_gemm2_kernel(const float* __restrict__ soft,
                 const float* __restrict__ x,
                 const float* __restrict__ mem,
                 float* __restrict__ cen)
{
    constexpr int BK = 16;
    int bt = blockIdx.z >> 2, s = blockIdx.z & 3;
    int b = bt >> 2, t = bt & 3;
    const float* A = soft + (size_t)bt * NC * N4;
    const float* Bp = (t < 3) ? (mem + (size_t)(b * 3 + t) * N4 * CC)
                              : (x + (size_t)b * N4 * CC);
    float* Cp = cen + (size_t)bt * NC * CC;

    __shared__ float As[BK][68];
    __shared__ float Bs[BK][132];
    int tid = threadIdx.x;
    int tx = tid & 15, ty = tid >> 4;
    int m0 = blockIdx.y * 64, c0 = blockIdx.x * 128;
    int ra = tid >> 2, ca = (tid & 3) << 2;
    int kb = tid >> 5, cc = (tid & 31) << 2;
    float acc[4][8] = {};
    int kstart = s * 1024, kend = kstart + 1024;
    for (int k0 = kstart; k0 < kend; k0 += BK) {
        int mA = m0 + ra;
        float4 av = make_float4(0.f, 0.f, 0.f, 0.f);
        if (mA < NC) av = *(const float4*)(A + (size_t)mA * N4 + k0 + ca);
        float4 bv0 = *(const float4*)(Bp + (size_t)(k0 + kb) * CC + c0 + cc);
        float4 bv1 = *(const float4*)(Bp + (size_t)(k0 + kb + 8) * CC + c0 + cc);
        __syncthreads();
        As[ca + 0][ra] = av.x; As[ca + 1][ra] = av.y;
        As[ca + 2][ra] = av.z; As[ca + 3][ra] = av.w;
        Bs[kb][cc + 0] = bv0.x; Bs[kb][cc + 1] = bv0.y;
        Bs[kb][cc + 2] = bv0.z; Bs[kb][cc + 3] = bv0.w;
        Bs[kb + 8][cc + 0] = bv1.x; Bs[kb + 8][cc + 1] = bv1.y;
        Bs[kb + 8][cc + 2] = bv1.z; Bs[kb + 8][cc + 3] = bv1.w;
        __syncthreads();
        #pragma unroll
        for (int kk = 0; kk < BK; kk++) {
            float a[4], bb[8];
            *(float4*)&a[0]  = *(const float4*)&As[kk][ty * 4];
            *(float4*)&bb[0] = *(const float4*)&Bs[kk][tx * 8];
            *(float4*)&bb[4] = *(const float4*)&Bs[kk][tx * 8 + 4];
            #pragma unroll
            for (int i = 0; i < 4; i++)
                #pragma unroll
                for (int j = 0; j < 8; j++)
                    acc[i][j] += a[i] * bb[j];
        }
    }
    #pragma unroll
    for (int i = 0; i < 4; i++) {
        int m = m0 + ty * 4 + i;
        if (m >= NC) continue;
        #pragma unroll
        for (int j = 0; j < 8; j++)
            atomicAdd(&Cp[(size_t)m * CC + c0 + tx * 8 + j], acc[i][j]);
    }
}

// ---- C_in gating + LayerNorm ----
__global__ void cin_kernel(const float* __restrict__ cen,
                           const float* __restrict__ alpha,
                           const float* __restrict__ beta,
                           const float* __restrict__ nw,
                           const float* __restrict__ nb,
                           float* __restrict__ cinln)
{
    __shared__ float sbuf[256];
    int bk = blockIdx.x;
    int b = bk / NC, k = bk % NC;
    int c = threadIdx.x;
    float last = cen[((size_t)(b * TT4 + 3) * NC + k) * CC + c];
    float pv[3];
    #pragma unroll
    for (int t = 0; t < 3; t++)
        pv[t] = cen[((size_t)(b * TT4 + t) * NC + k) * CC + c];
    float nl = block_reduce_sum(last * last, sbuf);
    float al = alpha[0], be = beta[0];
    float g[3];
    #pragma unroll
    for (int t = 0; t < 3; t++) {
        float dt = block_reduce_sum(last * pv[t], sbuf);
        float np = block_reduce_sum(pv[t] * pv[t], sbuf);
        float denom = fmaxf(sqrtf(nl) * sqrtf(np), 1e-8f);
        g[t] = 1.f / (1.f + expf(-(be + al * dt / denom)));
    }
    float cin = last + g[0] * pv[0] + g[1] * pv[1] + g[2] * pv[2];
    float mean = block_reduce_sum(cin, sbuf) * (1.f / CC);
    float d = cin - mean;
    float var = block_reduce_sum(d * d, sbuf) * (1.f / CC);
    cinln[((size_t)b * NC + k) * CC + c] = d * rsqrtf(var + 1e-5f) * nw[c] + nb[c];
}

// ---- attention ----
__global__ void attn_kernel(const float* __restrict__ q,
                            const float* __restrict__ kbuf,
                            const float* __restrict__ vbuf,
                            float* __restrict__ o)
{
    __shared__ float kh[NC * 33];
    __shared__ float vh[NC * 33];
    int b = blockIdx.z, h = blockIdx.y;
    int tid = threadIdx.x;
    int warp = tid >> 5, lane = tid & 31;
    for (int idx = tid; idx < NC * HD; idx += blockDim.x) {
        int kk = idx / HD, d = idx % HD;
        kh[kk * 33 + d] = kbuf[((size_t)b * NC + kk) * CC + h * HD + d];
        vh[kk * 33 + d] = vbuf[((size_t)b * NC + kk) * CC + h * HD + d];
    }
    __syncthreads();
    const unsigned FULL = 0xffffffffu;
    for (int ni = warp; ni < 256; ni += 8) {
        int n = blockIdx.x * 256 + ni;
        float qv = q[((size_t)b * N4 + n) * CC + h * HD + lane];
        float lg[5];
        #pragma unroll
        for (int i = 0; i < 5; i++) {
            int kk = lane + 32 * i;
            int kks = (kk < NC) ? kk : (NC - 1);
            float acc = 0.f;
            #pragma unroll
            for (int d = 0; d < 32; d++) {
                float qd = __shfl_sync(FULL, qv, d);
                acc += qd * kh[kks * 33 + d];
            }
            lg[i] = (kk < NC) ? acc : -3.4e38f;
        }
        float mx = lg[0];
        #pragma unroll
        for (int i = 1; i < 5; i++) mx = fmaxf(mx, lg[i]);
        #pragma unroll
        for (int off = 16; off > 0; off >>= 1)
            mx = fmaxf(mx, __shfl_xor_sync(FULL, mx, off));
        float p[5], s = 0.f;
        #pragma unroll
        for (int i = 0; i < 5; i++) { p[i] = expf(lg[i] - mx); s += p[i]; }
        #pragma unroll
        for (int off = 16; off > 0; off >>= 1)
            s += __shfl_xor_sync(FULL, s, off);
        float inv = 1.f / s;
        float od = 0.f;
        #pragma unroll
        for (int i = 0; i < 5; i++) {
            float pi = p[i] * inv;
            #pragma unroll
            for (int l = 0; l < 32; l++) {
                float a = __shfl_sync(FULL, pi, l);
                int kk = l + 32 * i;
                if (kk < NC) od += a * vh[kk * 33 + lane];
            }
        }
        o[((size_t)b * N4 + n) * CC + h * HD + lane] = od;
    }
}

// ---- out = base + LN(xin) ----
__global__ void ln_add_kernel(const float* __restrict__ base,
                              const float* __restrict__ xin,
                              const float* __restrict__ nw,
                              const float* __restrict__ nb,
                              float* __restrict__ out)
{
    __shared__ float sbuf[256];
    size_t row = blockIdx.x;
    int c = threadIdx.x;
    float v = xin[row * CC + c];
    float mean = block_reduce_sum(v, sbuf) * (1.f / CC);
    float d = v - mean;
    float var = block_reduce_sum(d * d, sbuf) * (1.f / CC);
    out[row * CC + c] = base[row * CC + c] + d * rsqrtf(var + 1e-5f) * nw[c] + nb[c];
}

// ---- out = base + LN(xin), also emit bf16 hi/lo split ----
__global__ void ln_add_split_kernel(const float* __restrict__ base,
                                    const float* __restrict__ xin,
                                    const float* __restrict__ nw,
                                    const float* __restrict__ nb,
                                    float* __restrict__ out,
                                    __nv_bfloat16* __restrict__ ohi,
                                    __nv_bfloat16* __restrict__ olo)
{
    __shared__ float sbuf[256];
    size_t row = blockIdx.x;
    int c = threadIdx.x;
    float v = xin[row * CC + c];
    float mean = block_reduce_sum(v, sbuf) * (1.f / CC);
    float d = v - mean;
    float var = block_reduce_sum(d * d, sbuf) * (1.f / CC);
    float r = base[row * CC + c] + d * rsqrtf(var + 1e-5f) * nw[c] + nb[c];
    size_t idx = row * CC + c;
    out[idx] = r;
    __nv_bfloat16 h = __float2bfloat16(r);
    ohi[idx] = h;
    olo[idx] = __float2bfloat16(r - __bfloat162float(h));
}

// ---- depthwise conv + GELU -> bf16 hi/lo ----
__global__ void dwconv_gelu_bf16_kernel(const float* __restrict__ h1,
                                        const float* __restrict__ dw_w,
                                        const float* __restrict__ dw_b,
                                        __nv_bfloat16* __restrict__ gh,
                                        __nv_bfloat16* __restrict__ gl)
{
    int idx = blockIdx.x * blockDim.x + threadIdx.x;
    if (idx >= BB * N4 * HID) return;
    int ch = idx & (HID - 1);
    int r = idx >> 10;
    int n = r & (N4 - 1);
    int b = r >> 12;
    int y = n >> 6, x = n & 63;
    float acc = dw_b[ch];
    #pragma unroll
    for (int dy = 0; dy < 3; dy++) {
        int yy = y + dy - 1;
        if (yy < 0 || yy >= HH) continue;
        #pragma unroll
        for (int dx = 0; dx < 3; dx++) {
            int xx = x + dx - 1;
            if (xx < 0 || xx >= WW) continue;
            acc += h1[((size_t)b * N4 + yy * WW + xx) * HID + ch] *
                   dw_w[ch * 9 + dy * 3 + dx];
        }
    }
    float v = 0.5f * acc * (1.0f + erff(acc * 0.70710678118654752f));
    __nv_bfloat16 h = __float2bfloat16(v);
    gh[idx] = h;
    gl[idx] = __float2bfloat16(v - __bfloat162float(h));
}

// ================= host launcher =================
extern "C" void kernel_launch(void* const* d_in, const int* in_sizes, int n_in,
                              void* d_out, int out_size)
{
    const float* x      = (const float*)d_in[0];
    const float* z      = (const float*)d_in[1];
    const float* mem    = (const float*)d_in[2];
    const float* cw     = (const float*)d_in[3];
    const float* p1     = (const float*)d_in[4];
    const float* tdt1   = (const float*)d_in[5];
    const float* p2     = (const float*)d_in[6];
    const float* tdt2   = (const float*)d_in[7];
    const float* alpha  = (const float*)d_in[8];
    const float* beta   = (const float*)d_in[9];
    const float* q_w    = (const float*)d_in[10];
    const float* q_b    = (const float*)d_in[11];
    const float* k_w    = (const float*)d_in[12];
    const float* k_b    = (const float*)d_in[13];
    const float* v_w    = (const float*)d_in[14];
    const float* v_b    = (const float*)d_in[15];
    const float* proj_w = (const float*)d_in[16];
    const float* proj_b = (const float*)d_in[17];
    const float* norm_w = (const float*)d_in[18];
    const float* norm_b = (const float*)d_in[19];
    const float* fc1_w  = (const float*)d_in[20];
    const float* fc1_b  = (const float*)d_in[21];
    const float* dw_w   = (const float*)d_in[22];
    const float* dw_b   = (const float*)d_in[23];
    const float* fc2_w  = (const float*)d_in[24];
    const float* fc2_b  = (const float*)d_in[25];

    float* out0 = (float*)d_out;
    float* cxz  = out0 + OUT0_ELEMS;
    float* ctr  = out0 + OUT0_ELEMS + CXZ_ELEMS;

    float *cl, *az, *ac, *soft, *cen, *cinln, *kb, *vb, *qb, *ob, *oproj,
          *out1, *h1, *h2;
    __nv_bfloat16 *xh, *xl, *obh, *obl, *o1h, *o1l, *gh, *gl;
    __nv_bfloat16 *qwh, *qwl, *pwh, *pwl, *f1h, *f1l, *f2h, *f2l;
    cudaGetSymbolAddress((void**)&cl,    g_cl);
    cudaGetSymbolAddress((void**)&az,    g_az);
    cudaGetSymbolAddress((void**)&ac,    g_ac);
    cudaGetSymbolAddress((void**)&soft,  g_soft);
    cudaGetSymbolAddress((void**)&cen,   g_cen);
    cudaGetSymbolAddress((void**)&cinln, g_cinln);
    cudaGetSymbolAddress((void**)&kb,    g_kbuf);
    cudaGetSymbolAddress((void**)&vb,    g_vbuf);
    cudaGetSymbolAddress((void**)&qb,    g_q);
    cudaGetSymbolAddress((void**)&ob,    g_o);
    cudaGetSymbolAddress((void**)&oproj, g_oproj);
    cudaGetSymbolAddress((void**)&out1,  g_out1);
    cudaGetSymbolAddress((void**)&h1,    g_h1);
    cudaGetSymbolAddress((void**)&h2,    g_h2);
    cudaGetSymbolAddress((void**)&xh,  g_xh);  cudaGetSymbolAddress((void**)&xl,  g_xl);
    cudaGetSymbolAddress((void**)&obh, g_obh); cudaGetSymbolAddress((void**)&obl, g_obl);
    cudaGetSymbolAddress((void**)&o1h, g_o1h); cudaGetSymbolAddress((void**)&o1l, g_o1l);
    cudaGetSymbolAddress((void**)&gh,  g_gh);  cudaGetSymbolAddress((void**)&gl,  g_gl);
    cudaGetSymbolAddress((void**)&qwh, g_qwh); cudaGetSymbolAddress((void**)&qwl, g_qwl);
    cudaGetSymbolAddress((void**)&pwh, g_pwh); cudaGetSymbolAddress((void**)&pwl, g_pwl);
    cudaGetSymbolAddress((void**)&f1h, g_f1h); cudaGetSymbolAddress((void**)&f1l, g_f1l);
    cudaGetSymbolAddress((void**)&f2h, g_f2h); cudaGetSymbolAddress((void**)&f2l, g_f2l);

    // 0) bf16 splits of static inputs
    cvt_split_kernel<<<2097152 / 4 / 256, 256>>>(x, xh, xl, 2097152);
    cvt_split_kernel<<<65536 / 4 / 256, 256>>>(q_w, qwh, qwl, 65536);
    cvt_split_kernel<<<65536 / 4 / 256, 256>>>(proj_w, pwh, pwl, 65536);
    cvt_split_kernel<<<262144 / 4 / 256, 256>>>(fc1_w, f1h, f1l, 262144);
    cvt_split_kernel<<<262144 / 4 / 256, 256>>>(fc2_w, f2h, f2l, 262144);

    // 1) cl
    cl_gemm2_kernel<<<dim3(N4 / 128, 3, BB * TT4), 256>>>(cw, x, mem, cl);
    // 2) prompt cos + scaling
    prompt_scale_kernel<<<dim3(TNE / 256, 1, BB), 256>>>(z, cl, p1, p2, az, ac);
    // 3) combine GEMM -> cluster_x_z + center
    comb_gemm2_kernel<<<dim3(TNE / 128, 3, BB), 256>>>(tdt1, tdt2, az, ac, cxz, ctr);
    // 4) softmax
    softmax_kernel<<<BB * TT4 * NC, 256>>>(cxz, soft);
    // 5) cen
    zero_cen_kernel<<<(307200 + 255) / 256, 256>>>(cen);
    cen_gemm2_kernel<<<dim3(CC / 128, 3, BB * TT4 * 4), 256>>>(soft, x, mem, cen);
    // 6) gating + LN
    cin_kernel<<<BB * NC, 256>>>(cen, alpha, beta, norm_w, norm_b, cinln);
    // 7) k/v projections
    gemm_tb_kernel<<<dim3(CC / OBN, (BB * NC + OBM - 1) / OBM), 256>>>(
        cinln, k_w, k_b, kb, BB * NC, CC, CC, 1.f);
    gemm_tb_kernel<<<dim3(CC / OBN, (BB * NC + OBM - 1) / OBM), 256>>>(
        cinln, v_w, v_b, vb, BB * NC, CC, CC, 1.f);
    // 8) q projection (HMMA bf16-split)
    hmma_gemm_kernel<<<dim3(2, 64), 256>>>(
        xh, xl, qwh, qwl, q_b, qb, CC, CC, 0.17677669529663687f);
    // 9) attention
    attn_kernel<<<dim3(N4 / 256, NH, BB), 256>>>(qb, kb, vb, ob);
    cvt_split_kernel<<<2097152 / 4 / 256, 256>>>(ob, obh, obl, 2097152);
    // 10) output projection (HMMA)
    hmma_gemm_kernel<<<dim3(2, 64), 256>>>(
        obh, obl, pwh, pwl, proj_b, oproj, CC, CC, 1.f);
    // 11) out1 = x + LN(oproj), + bf16 split
    ln_add_split_kernel<<<BB * N4, 256>>>(x, oproj, norm_w, norm_b, out1, o1h, o1l);
    // 12) fc1 (HMMA)
    hmma_gemm_kernel<<<dim3(8, 64), 256>>>(
        o1h, o1l, f1h, f1l, fc1_b, h1, HID, CC, 1.f);
    // 13) depthwise conv + gelu -> bf16 split
    dwconv_gelu_bf16_kernel<<<(BB * N4 * HID + 255) / 256, 256>>>(h1, dw_w, dw_b, gh, gl);
    // 14) fc2 (HMMA)
    hmma_gemm_kernel<<<dim3(2, 64), 256>>>(
        gh, gl, f2h, f2l, fc2_b, h2, CC, HID, 1.f);
    // 15) out = out1 + LN(h2)
    ln_add_kernel<<<BB * N4, 256>>>(out1, h2, norm_w, norm_b, out0);
}